// round 3
// baseline (speedup 1.0000x reference)
#include <cuda_runtime.h>
#include <math.h>

#define C_DIM   1024
#define N_HEADS 16
#define HD      64
#define N_LAYERS 6
#define HID_DIM 4096
#define BATCH   2
#define SEQ     2048
#define NROWS   (BATCH*SEQ)
#define WIN     1000

// ---------------- scratch (no allocations allowed) ----------------
__device__ float g_x   [NROWS * C_DIM];
__device__ float g_qkv [NROWS * 3 * C_DIM];
__device__ float g_attn[NROWS * C_DIM];
__device__ float g_tmp [NROWS * C_DIM];
__device__ float g_hid [NROWS * HID_DIM];

// ---------------- block-wide sum reduce (256 threads) ----------------
__device__ __forceinline__ float blk_sum(float v, float* sh) {
    int tid = threadIdx.x;
    sh[tid] = v;
    __syncthreads();
#pragma unroll
    for (int s = 128; s > 0; s >>= 1) {
        if (tid < s) sh[tid] += sh[tid + s];
        __syncthreads();
    }
    float r = sh[0];
    __syncthreads();
    return r;
}

// ---------------- input LN + sinusoidal positional embedding ----------------
__global__ __launch_bounds__(256) void embed_ln_kernel(
    const float* __restrict__ x, const float* __restrict__ g,
    const float* __restrict__ b, float* __restrict__ out)
{
    __shared__ float sh[256];
    int r = blockIdx.x;            // row in [0, NROWS)
    int t = r % SEQ;               // time position
    const float* xr = x + (size_t)r * C_DIM;
    int tid = threadIdx.x;

    float v[4];
    float s = 0.f;
#pragma unroll
    for (int i = 0; i < 4; i++) { v[i] = xr[tid + 256 * i]; s += v[i]; }
    float mean = blk_sum(s, sh) * (1.0f / C_DIM);
    float d2 = 0.f;
#pragma unroll
    for (int i = 0; i < 4; i++) { float d = v[i] - mean; d2 += d * d; }
    float var = blk_sum(d2, sh) * (1.0f / C_DIM);
    float inv = rsqrtf(var + 1e-5f);

    const float kln = 9.2103403719761836f / 511.0f; // ln(10000)/511
    float tf = (float)t;
#pragma unroll
    for (int i = 0; i < 4; i++) {
        int c = tid + 256 * i;
        float pos;
        if (c < 512) {
            float ph = tf * expf(-((float)c) * kln);
            pos = cosf(ph);
        } else {
            float ph = tf * expf(-((float)(c - 512)) * kln);
            pos = sinf(ph);
        }
        out[(size_t)r * C_DIM + c] = (v[i] - mean) * inv * g[c] + b[c] + pos;
    }
}

// ---------------- y = LN(xin + add)*g + b ----------------
__global__ __launch_bounds__(256) void add_ln_kernel(
    const float* __restrict__ xin, const float* __restrict__ add,
    const float* __restrict__ g, const float* __restrict__ b,
    float* __restrict__ out)
{
    __shared__ float sh[256];
    int r = blockIdx.x;
    const float* xr = xin + (size_t)r * C_DIM;
    const float* ar = add + (size_t)r * C_DIM;
    int tid = threadIdx.x;

    float v[4];
    float s = 0.f;
#pragma unroll
    for (int i = 0; i < 4; i++) {
        int c = tid + 256 * i;
        v[i] = xr[c] + ar[c];
        s += v[i];
    }
    float mean = blk_sum(s, sh) * (1.0f / C_DIM);
    float d2 = 0.f;
#pragma unroll
    for (int i = 0; i < 4; i++) { float d = v[i] - mean; d2 += d * d; }
    float var = blk_sum(d2, sh) * (1.0f / C_DIM);
    float inv = rsqrtf(var + 1e-5f);
#pragma unroll
    for (int i = 0; i < 4; i++) {
        int c = tid + 256 * i;
        out[(size_t)r * C_DIM + c] = (v[i] - mean) * inv * g[c] + b[c];
    }
}

// ---------------- SGEMM: C[M,N] = A[M,K] * B[N,K]^T + bias (+optional exact GELU) ----
// 128x128 tile, BK=16, 256 threads, 8x8 per thread.
template<int DO_GELU>
__global__ __launch_bounds__(256) void sgemm_nt(
    const float* __restrict__ A, const float* __restrict__ Bw,
    const float* __restrict__ bias, float* __restrict__ C,
    int M, int N, int K)
{
    __shared__ float As[16][132];
    __shared__ float Bs[16][132];
    const int tid = threadIdx.x;
    const int tx = tid & 15;
    const int ty = tid >> 4;
    const int lr = tid >> 1;          // 0..127
    const int lk = (tid & 1) << 3;    // 0 or 8

    const float* Ap = A  + ((size_t)(blockIdx.y * 128 + lr)) * K + lk;
    const float* Bp = Bw + ((size_t)(blockIdx.x * 128 + lr)) * K + lk;

    float acc[8][8];
#pragma unroll
    for (int i = 0; i < 8; i++)
#pragma unroll
        for (int j = 0; j < 8; j++) acc[i][j] = 0.f;

    for (int k0 = 0; k0 < K; k0 += 16) {
        float4 a0 = *(const float4*)(Ap + k0);
        float4 a1 = *(const float4*)(Ap + k0 + 4);
        float4 b0 = *(const float4*)(Bp + k0);
        float4 b1 = *(const float4*)(Bp + k0 + 4);
        As[lk + 0][lr] = a0.x; As[lk + 1][lr] = a0.y; As[lk + 2][lr] = a0.z; As[lk + 3][lr] = a0.w;
        As[lk + 4][lr] = a1.x; As[lk + 5][lr] = a1.y; As[lk + 6][lr] = a1.z; As[lk + 7][lr] = a1.w;
        Bs[lk + 0][lr] = b0.x; Bs[lk + 1][lr] = b0.y; Bs[lk + 2][lr] = b0.z; Bs[lk + 3][lr] = b0.w;
        Bs[lk + 4][lr] = b1.x; Bs[lk + 5][lr] = b1.y; Bs[lk + 6][lr] = b1.z; Bs[lk + 7][lr] = b1.w;
        __syncthreads();
#pragma unroll
        for (int kk = 0; kk < 16; kk++) {
            float4 av0 = *(const float4*)&As[kk][ty * 8];
            float4 av1 = *(const float4*)&As[kk][ty * 8 + 4];
            float4 bv0 = *(const float4*)&Bs[kk][tx * 8];
            float4 bv1 = *(const float4*)&Bs[kk][tx * 8 + 4];
            float ar[8] = {av0.x, av0.y, av0.z, av0.w, av1.x, av1.y, av1.z, av1.w};
            float br[8] = {bv0.x, bv0.y, bv0.z, bv0.w, bv1.x, bv1.y, bv1.z, bv1.w};
#pragma unroll
            for (int i = 0; i < 8; i++)
#pragma unroll
                for (int j = 0; j < 8; j++)
                    acc[i][j] = fmaf(ar[i], br[j], acc[i][j]);
        }
        __syncthreads();
    }

    const int row0 = blockIdx.y * 128 + ty * 8;
    const int col0 = blockIdx.x * 128 + tx * 8;
    float bb[8];
#pragma unroll
    for (int j = 0; j < 8; j++) bb[j] = bias[col0 + j];
#pragma unroll
    for (int i = 0; i < 8; i++) {
        float* cp = C + (size_t)(row0 + i) * N + col0;
#pragma unroll
        for (int j = 0; j < 8; j++) {
            float v = acc[i][j] + bb[j];
            if (DO_GELU) v = 0.5f * v * (1.f + erff(v * 0.70710678118654752f));
            cp[j] = v;
        }
    }
}

// ---------------- sliding-window causal attention (flash-style, fp32) ----------------
// qkv: [NROWS, 3*C_DIM] with q|k|v packed. One thread per query.
// grid: (SEQ/128, N_HEADS, BATCH), block: 128.
// Past zero-token: k = bk, v = bv (bias slices), valid when t <= 999.
__global__ __launch_bounds__(128) void attn_kernel(
    const float* __restrict__ qkv, const float* __restrict__ bqkv_l,
    float* __restrict__ out)
{
    const int KB = 32;
    __shared__ float Ks[KB][HD];
    __shared__ float Vs[KB][HD];

    const int b = blockIdx.z;
    const int h = blockIdx.y;
    const int tq = blockIdx.x * 128 + threadIdx.x;
    const float scale = 0.125f; // 1/sqrt(64)

    float q[HD];
    const float* qp = qkv + (size_t)(b * SEQ + tq) * (3 * C_DIM) + h * HD;
#pragma unroll
    for (int d = 0; d < HD; d += 4) {
        float4 t4 = *(const float4*)(qp + d);
        q[d] = t4.x * scale; q[d + 1] = t4.y * scale;
        q[d + 2] = t4.z * scale; q[d + 3] = t4.w * scale;
    }

    float o[HD];
    float mmax, lsum;
    const float* bk = bqkv_l + C_DIM + h * HD;
    const float* bv = bqkv_l + 2 * C_DIM + h * HD;
    if (tq <= WIN - 1) {                 // past token valid (delta = t+1 <= 1000)
        float s = 0.f;
#pragma unroll
        for (int d = 0; d < HD; d++) s += q[d] * bk[d];
        mmax = s; lsum = 1.f;
#pragma unroll
        for (int d = 0; d < HD; d++) o[d] = bv[d];
    } else {
        mmax = -3.0e38f; lsum = 0.f;
#pragma unroll
        for (int d = 0; d < HD; d++) o[d] = 0.f;
    }

    const int qlo = blockIdx.x * 128;
    const int jstart = (qlo - WIN) > 0 ? (qlo - WIN) : 0;
    const int jend = qlo + 127;          // < SEQ always

    for (int j0 = jstart; j0 <= jend; j0 += KB) {
        __syncthreads();
        // cooperative load of KB keys & values for this head
#pragma unroll
        for (int i = 0; i < 4; i++) {
            int f = threadIdx.x + i * 128;   // 0..511 float4 slots
            int row = f >> 4;
            int dc = (f & 15) << 2;
            int j = j0 + row;
            float4 kv4 = {0.f, 0.f, 0.f, 0.f}, vv4 = {0.f, 0.f, 0.f, 0.f};
            if (j <= jend) {
                const float* kp = qkv + (size_t)(b * SEQ + j) * (3 * C_DIM) + C_DIM + h * HD + dc;
                kv4 = *(const float4*)kp;
                vv4 = *(const float4*)(kp + C_DIM);
            }
            *(float4*)&Ks[row][dc] = kv4;
            *(float4*)&Vs[row][dc] = vv4;
        }
        __syncthreads();

        for (int jj = 0; jj < KB; jj++) {
            int j = j0 + jj;
            if (j > jend) break;                 // uniform
            if (j > tq || j < tq - WIN) continue; // per-thread window mask
            float s = 0.f;
#pragma unroll
            for (int d = 0; d < HD; d++) s += q[d] * Ks[jj][d];
            if (s <= mmax) {
                float p = __expf(s - mmax);
                lsum += p;
#pragma unroll
                for (int d = 0; d < HD; d++) o[d] += p * Vs[jj][d];
            } else {
                float c = __expf(mmax - s);
                lsum = lsum * c + 1.f;
#pragma unroll
                for (int d = 0; d < HD; d++) o[d] = o[d] * c + Vs[jj][d];
                mmax = s;
            }
        }
    }

    float rinv = 1.f / lsum;
    float* op = out + (size_t)(b * SEQ + tq) * C_DIM + h * HD;
#pragma unroll
    for (int d = 0; d < HD; d += 4) {
        float4 w;
        w.x = o[d] * rinv; w.y = o[d + 1] * rinv;
        w.z = o[d + 2] * rinv; w.w = o[d + 3] * rinv;
        *(float4*)(op + d) = w;
    }
}

// ---------------- launcher ----------------
extern "C" void kernel_launch(void* const* d_in, const int* in_sizes, int n_in,
                              void* d_out, int out_size)
{
    const float* x        = (const float*)d_in[0];
    const float* norm_g   = (const float*)d_in[1];
    const float* norm_b   = (const float*)d_in[2];
    const float* Wqkv     = (const float*)d_in[3];
    const float* bqkv     = (const float*)d_in[4];
    const float* Wo       = (const float*)d_in[5];
    const float* bo       = (const float*)d_in[6];
    const float* ln1_g    = (const float*)d_in[7];
    const float* ln1_b    = (const float*)d_in[8];
    const float* ln2_g    = (const float*)d_in[9];
    const float* ln2_b    = (const float*)d_in[10];
    const float* W1       = (const float*)d_in[11];
    const float* b1       = (const float*)d_in[12];
    const float* W2       = (const float*)d_in[13];
    const float* b2       = (const float*)d_in[14];
    float* out = (float*)d_out;

    float *gx, *gqkv, *gattn, *gtmp, *ghid;
    cudaGetSymbolAddress((void**)&gx,    g_x);
    cudaGetSymbolAddress((void**)&gqkv,  g_qkv);
    cudaGetSymbolAddress((void**)&gattn, g_attn);
    cudaGetSymbolAddress((void**)&gtmp,  g_tmp);
    cudaGetSymbolAddress((void**)&ghid,  g_hid);

    embed_ln_kernel<<<NROWS, 256>>>(x, norm_g, norm_b, gx);

    for (int l = 0; l < N_LAYERS; l++) {
        const float* Wqkv_l = Wqkv + (size_t)l * 3 * C_DIM * C_DIM;
        const float* bqkv_l = bqkv + (size_t)l * 3 * C_DIM;
        const float* Wo_l   = Wo   + (size_t)l * C_DIM * C_DIM;
        const float* bo_l   = bo   + (size_t)l * C_DIM;
        const float* W1_l   = W1   + (size_t)l * HID_DIM * C_DIM;
        const float* b1_l   = b1   + (size_t)l * HID_DIM;
        const float* W2_l   = W2   + (size_t)l * C_DIM * HID_DIM;
        const float* b2_l   = b2   + (size_t)l * C_DIM;

        // qkv = x @ Wqkv^T + bqkv   [4096, 3072]
        sgemm_nt<0><<<dim3(3 * C_DIM / 128, NROWS / 128), 256>>>(
            gx, Wqkv_l, bqkv_l, gqkv, NROWS, 3 * C_DIM, C_DIM);

        // attention
        attn_kernel<<<dim3(SEQ / 128, N_HEADS, BATCH), 128>>>(gqkv, bqkv_l, gattn);

        // o = attn @ Wo^T + bo      [4096, 1024]
        sgemm_nt<0><<<dim3(C_DIM / 128, NROWS / 128), 256>>>(
            gattn, Wo_l, bo_l, gtmp, NROWS, C_DIM, C_DIM);

        // x = LN(x + o; ln1)
        add_ln_kernel<<<NROWS, 256>>>(gx, gtmp, ln1_g + l * C_DIM, ln1_b + l * C_DIM, gx);

        // hid = gelu(x @ W1^T + b1) [4096, 4096]
        sgemm_nt<1><<<dim3(HID_DIM / 128, NROWS / 128), 256>>>(
            gx, W1_l, b1_l, ghid, NROWS, HID_DIM, C_DIM);

        // ff = hid @ W2^T + b2      [4096, 1024]
        sgemm_nt<0><<<dim3(C_DIM / 128, NROWS / 128), 256>>>(
            ghid, W2_l, b2_l, gtmp, NROWS, C_DIM, HID_DIM);

        // x = LN(x + ff; ln2)  (last layer writes straight to d_out)
        float* dst = (l == N_LAYERS - 1) ? out : gx;
        add_ln_kernel<<<NROWS, 256>>>(gx, gtmp, ln2_g + l * C_DIM, ln2_b + l * C_DIM, dst);
    }
}

// round 8
// speedup vs baseline: 2.1133x; 2.1133x over previous
#include <cuda_runtime.h>
#include <cuda_bf16.h>
#include <math.h>
#include <stdint.h>

#define C_DIM   1024
#define N_HEADS 16
#define HD      64
#define N_LAYERS 6
#define HID_DIM 4096
#define BATCH   2
#define SEQ     2048
#define NROWS   (BATCH*SEQ)
#define WIN     1000

// ================= scratch (no allocations allowed) =================
__device__ float g_x   [NROWS * C_DIM];
__device__ float g_qkv [NROWS * 3 * C_DIM];
__device__ float g_tmp [NROWS * C_DIM];
__device__ __nv_bfloat16 g_xh[NROWS * C_DIM],  g_xl[NROWS * C_DIM];
__device__ __nv_bfloat16 g_ah[NROWS * C_DIM],  g_al[NROWS * C_DIM];
__device__ __nv_bfloat16 g_hh[NROWS * HID_DIM], g_hl[NROWS * HID_DIM];
// per-layer split weight staging (reused for Wqkv / Wo / W1 / W2; max 4M elems)
#define WMAX (HID_DIM * C_DIM)
__device__ __nv_bfloat16 g_wh[WMAX], g_wl[WMAX];

// ================= helpers =================
__device__ __forceinline__ uint32_t smem_to_u32(const void* p) {
    uint32_t a;
    asm("{ .reg .u64 t; cvta.to.shared.u64 t, %1; cvt.u32.u64 %0, t; }" : "=r"(a) : "l"(p));
    return a;
}
#define SMEM_SWIZZLE_128B(x) ((x) ^ (((x) >> 3) & 0x70))

__device__ __forceinline__ void ldsm4(uint32_t* r, uint32_t addr) {
    asm volatile("ldmatrix.sync.aligned.m8n8.x4.shared.b16 {%0,%1,%2,%3}, [%4];"
                 : "=r"(r[0]), "=r"(r[1]), "=r"(r[2]), "=r"(r[3]) : "r"(addr));
}
__device__ __forceinline__ void mma16816(float* d, const uint32_t* a, uint32_t b0, uint32_t b1) {
    asm volatile("mma.sync.aligned.m16n8k16.row.col.f32.bf16.bf16.f32 "
                 "{%0,%1,%2,%3}, {%4,%5,%6,%7}, {%8,%9}, {%0,%1,%2,%3};"
                 : "+f"(d[0]), "+f"(d[1]), "+f"(d[2]), "+f"(d[3])
                 : "r"(a[0]), "r"(a[1]), "r"(a[2]), "r"(a[3]), "r"(b0), "r"(b1));
}

__device__ __forceinline__ void split_pair(float v, __nv_bfloat16& hi, __nv_bfloat16& lo) {
    hi = __float2bfloat16(v);
    lo = __float2bfloat16(v - __bfloat162float(hi));
}

// ================= weight / tensor split kernel =================
__global__ void split_f32_kernel(const float* __restrict__ w, __nv_bfloat16* __restrict__ h,
                                 __nv_bfloat16* __restrict__ l, int n) {
    int i = blockIdx.x * blockDim.x + threadIdx.x;
    int stride = gridDim.x * blockDim.x;
    for (; i < n; i += stride) {
        float v = w[i];
        __nv_bfloat16 hi, lo;
        split_pair(v, hi, lo);
        h[i] = hi; l[i] = lo;
    }
}

// ================= block reduce =================
__device__ __forceinline__ float blk_sum(float v, float* sh) {
    int tid = threadIdx.x;
    sh[tid] = v; __syncthreads();
#pragma unroll
    for (int s = 128; s > 0; s >>= 1) { if (tid < s) sh[tid] += sh[tid + s]; __syncthreads(); }
    float r = sh[0]; __syncthreads();
    return r;
}

// ================= input LN + positional embedding (emits fp32 + split) ==========
__global__ __launch_bounds__(256) void embed_ln_kernel(
    const float* __restrict__ x, const float* __restrict__ g, const float* __restrict__ b,
    float* __restrict__ out, __nv_bfloat16* __restrict__ oh, __nv_bfloat16* __restrict__ ol)
{
    __shared__ float sh[256];
    int r = blockIdx.x, t = r % SEQ, tid = threadIdx.x;
    const float* xr = x + (size_t)r * C_DIM;
    float v[4]; float s = 0.f;
#pragma unroll
    for (int i = 0; i < 4; i++) { v[i] = xr[tid + 256 * i]; s += v[i]; }
    float mean = blk_sum(s, sh) * (1.0f / C_DIM);
    float d2 = 0.f;
#pragma unroll
    for (int i = 0; i < 4; i++) { float d = v[i] - mean; d2 += d * d; }
    float inv = rsqrtf(blk_sum(d2, sh) * (1.0f / C_DIM) + 1e-5f);
    const float kln = 9.2103403719761836f / 511.0f;
    float tf = (float)t;
#pragma unroll
    for (int i = 0; i < 4; i++) {
        int c = tid + 256 * i;
        float ph = (c < 512) ? tf * expf(-((float)c) * kln) : tf * expf(-((float)(c - 512)) * kln);
        float pos = (c < 512) ? cosf(ph) : sinf(ph);
        float y = (v[i] - mean) * inv * g[c] + b[c] + pos;
        size_t idx = (size_t)r * C_DIM + c;
        out[idx] = y;
        __nv_bfloat16 hi, lo; split_pair(y, hi, lo);
        oh[idx] = hi; ol[idx] = lo;
    }
}

// ================= y = LN(xin+add); optionally also emit split ====================
template<int SPLIT>
__global__ __launch_bounds__(256) void add_ln_kernel(
    const float* __restrict__ xin, const float* __restrict__ add,
    const float* __restrict__ g, const float* __restrict__ b,
    float* __restrict__ out, __nv_bfloat16* __restrict__ oh, __nv_bfloat16* __restrict__ ol)
{
    __shared__ float sh[256];
    int r = blockIdx.x, tid = threadIdx.x;
    const float* xr = xin + (size_t)r * C_DIM;
    const float* ar = add + (size_t)r * C_DIM;
    float v[4]; float s = 0.f;
#pragma unroll
    for (int i = 0; i < 4; i++) { int c = tid + 256 * i; v[i] = xr[c] + ar[c]; s += v[i]; }
    float mean = blk_sum(s, sh) * (1.0f / C_DIM);
    float d2 = 0.f;
#pragma unroll
    for (int i = 0; i < 4; i++) { float d = v[i] - mean; d2 += d * d; }
    float inv = rsqrtf(blk_sum(d2, sh) * (1.0f / C_DIM) + 1e-5f);
#pragma unroll
    for (int i = 0; i < 4; i++) {
        int c = tid + 256 * i;
        float y = (v[i] - mean) * inv * g[c] + b[c];
        size_t idx = (size_t)r * C_DIM + c;
        out[idx] = y;
        if (SPLIT) { __nv_bfloat16 hi, lo; split_pair(y, hi, lo); oh[idx] = hi; ol[idx] = lo; }
    }
}

// ================= split-bf16 HMMA GEMM (legacy mma.sync path) ===================
// C[M,N] = (Ah+Al)[M,K] * (Bh+Bl)[N,K]^T + bias  (3-term bf16 MMA, fp32 accum)
// CTA tile 128x128, BK=64 (SW128 128B rows), 2-stage cp.async, 8 warps (2x4),
// warp tile 64x32, mma.sync.m16n8k16 + ldmatrix (base ISA, works on compute_103).
// OUT_MODE 0: fp32 out + bias.   OUT_MODE 1: gelu(out+bias) -> bf16 hi/lo pair.
#define GEMM_SMEM_BYTES (1024 + 2 * 4 * 16384)

template<int OUT_MODE>
__global__ __launch_bounds__(256, 1) void gemm_hmma3(
    const __nv_bfloat16* __restrict__ Ah, const __nv_bfloat16* __restrict__ Al,
    const __nv_bfloat16* __restrict__ Bh, const __nv_bfloat16* __restrict__ Bl,
    const float* __restrict__ bias,
    float* __restrict__ Cf, __nv_bfloat16* __restrict__ Ch, __nv_bfloat16* __restrict__ Cl,
    int M, int N, int K)
{
    extern __shared__ char dsm[];
    const uint32_t tiles = (smem_to_u32(dsm) + 1023u) & ~1023u;
    const int tid = threadIdx.x;
    const int wid = tid >> 5;
    const int lid = tid & 31;
    const int warp_m = wid & 1;        // 2 M-warps * 64 rows
    const int warp_n = wid >> 1;       // 4 N-warps * 32 cols
    const int row0 = blockIdx.y * 128;
    const int col0 = blockIdx.x * 128;
    const int nchunk = K >> 6;         // K / 64

    const char* gsrc0 = (const char*)(Ah + (size_t)row0 * K);
    const char* gsrc1 = (const char*)(Al + (size_t)row0 * K);
    const char* gsrc2 = (const char*)(Bh + (size_t)col0 * K);
    const char* gsrc3 = (const char*)(Bl + (size_t)col0 * K);
    const size_t rowbytes = (size_t)K * 2;

    // load one 4-tile chunk (Ah|Al|Bh|Bl, each 128 rows x 128B, SW128) via cp.async
    auto load_chunk = [&](int c, int st) {
        const uint32_t sb = tiles + st * 65536;
        const size_t koff = (size_t)c * 128;    // 64 bf16 = 128 bytes per row
#pragma unroll
        for (int i = 0; i < 16; i++) {
            int u = tid + i * 256;              // 0..4095 16B units
            int t = u >> 10;                    // tile 0..3
            int r = (u >> 3) & 127;             // row
            int cb = (u & 7) * 16;              // byte col
            const char* g = (t == 0 ? gsrc0 : t == 1 ? gsrc1 : t == 2 ? gsrc2 : gsrc3)
                            + (size_t)r * rowbytes + koff + cb;
            uint32_t sa = sb + t * 16384 + SMEM_SWIZZLE_128B((uint32_t)(r * 128 + cb));
            asm volatile("cp.async.cg.shared.global [%0], [%1], 16;" :: "r"(sa), "l"(g));
        }
        asm volatile("cp.async.commit_group;");
    };

    float acc[4][4][4];
#pragma unroll
    for (int a = 0; a < 4; a++)
#pragma unroll
        for (int b = 0; b < 4; b++)
#pragma unroll
            for (int i = 0; i < 4; i++) acc[a][b][i] = 0.f;

    const int lane15 = lid & 15;
    const int lanehi = lid >> 4;       // 0/1 : low/high 16B unit within the k16 step
    const int xr = lane15 & 7;         // SW128 xor term for this lane's row

    load_chunk(0, 0);

    for (int c = 0; c < nchunk; c++) {
        const int st = c & 1;
        if (c + 1 < nchunk) {
            load_chunk(c + 1, st ^ 1);
            asm volatile("cp.async.wait_group 1;");
        } else {
            asm volatile("cp.async.wait_group 0;");
        }
        __syncthreads();

        const uint32_t sb = tiles + st * 65536;
        const uint32_t aBaseH = sb          + (uint32_t)(warp_m * 64 + lane15) * 128;
        const uint32_t aBaseL = sb + 16384  + (uint32_t)(warp_m * 64 + lane15) * 128;
        const uint32_t bBaseH = sb + 32768  + (uint32_t)(warp_n * 32 + lane15) * 128;
        const uint32_t bBaseL = sb + 49152  + (uint32_t)(warp_n * 32 + lane15) * 128;

#pragma unroll
        for (int ks = 0; ks < 4; ks++) {
            const uint32_t uoff = (uint32_t)(((ks * 2 + lanehi) ^ xr) * 16);
            uint32_t ah[4][4], al[4][4], bhv[2][4], blv[2][4];
#pragma unroll
            for (int mt = 0; mt < 4; mt++) {
                ldsm4(ah[mt], aBaseH + mt * 2048 + uoff);
                ldsm4(al[mt], aBaseL + mt * 2048 + uoff);
            }
#pragma unroll
            for (int pt = 0; pt < 2; pt++) {
                ldsm4(bhv[pt], bBaseH + pt * 2048 + uoff);
                ldsm4(blv[pt], bBaseL + pt * 2048 + uoff);
            }
#pragma unroll
            for (int mt = 0; mt < 4; mt++) {
#pragma unroll
                for (int nt = 0; nt < 4; nt++) {
                    const int pt = nt >> 1, o = nt & 1;
                    mma16816(acc[mt][nt], ah[mt], bhv[pt][o], bhv[pt][o + 2]);
                    mma16816(acc[mt][nt], ah[mt], blv[pt][o], blv[pt][o + 2]);
                    mma16816(acc[mt][nt], al[mt], bhv[pt][o], bhv[pt][o + 2]);
                }
            }
        }
        __syncthreads();
    }

    // epilogue
    const int lr = lid >> 2;
    const int lc = (lid & 3) * 2;
#pragma unroll
    for (int mt = 0; mt < 4; mt++) {
        const int row = row0 + warp_m * 64 + mt * 16 + lr;
#pragma unroll
        for (int nt = 0; nt < 4; nt++) {
            const int col = col0 + warp_n * 32 + nt * 8 + lc;
            const float b0 = bias[col], b1 = bias[col + 1];
            float v0 = acc[mt][nt][0] + b0, v1 = acc[mt][nt][1] + b1;
            float v2 = acc[mt][nt][2] + b0, v3 = acc[mt][nt][3] + b1;
            if (OUT_MODE == 0) {
                float2 w0; w0.x = v0; w0.y = v1;
                float2 w1; w1.x = v2; w1.y = v3;
                *(float2*)(Cf + (size_t)row * N + col) = w0;
                *(float2*)(Cf + (size_t)(row + 8) * N + col) = w1;
            } else {
                v0 = 0.5f * v0 * (1.f + erff(v0 * 0.70710678118654752f));
                v1 = 0.5f * v1 * (1.f + erff(v1 * 0.70710678118654752f));
                v2 = 0.5f * v2 * (1.f + erff(v2 * 0.70710678118654752f));
                v3 = 0.5f * v3 * (1.f + erff(v3 * 0.70710678118654752f));
                __nv_bfloat16 h0, l0, h1, l1, h2, l2, h3, l3;
                split_pair(v0, h0, l0); split_pair(v1, h1, l1);
                split_pair(v2, h2, l2); split_pair(v3, h3, l3);
                __nv_bfloat162 hh0; hh0.x = h0; hh0.y = h1;
                __nv_bfloat162 ll0; ll0.x = l0; ll0.y = l1;
                __nv_bfloat162 hh1; hh1.x = h2; hh1.y = h3;
                __nv_bfloat162 ll1; ll1.x = l2; ll1.y = l3;
                *(__nv_bfloat162*)(Ch + (size_t)row * N + col) = hh0;
                *(__nv_bfloat162*)(Cl + (size_t)row * N + col) = ll0;
                *(__nv_bfloat162*)(Ch + (size_t)(row + 8) * N + col) = hh1;
                *(__nv_bfloat162*)(Cl + (size_t)(row + 8) * N + col) = ll1;
            }
        }
    }
}

// ================= sliding-window causal attention (emits bf16 split) =============
__global__ __launch_bounds__(128) void attn_kernel(
    const float* __restrict__ qkv, const float* __restrict__ bqkv_l,
    __nv_bfloat16* __restrict__ oh, __nv_bfloat16* __restrict__ ol)
{
    const int KB = 32;
    __shared__ float Ks[KB][HD];
    __shared__ float Vs[KB][HD];

    const int b = blockIdx.z;
    const int h = blockIdx.y;
    const int tq = blockIdx.x * 128 + threadIdx.x;
    const float scale = 0.125f;

    float q[HD];
    const float* qp = qkv + (size_t)(b * SEQ + tq) * (3 * C_DIM) + h * HD;
#pragma unroll
    for (int d = 0; d < HD; d += 4) {
        float4 t4 = *(const float4*)(qp + d);
        q[d] = t4.x * scale; q[d + 1] = t4.y * scale;
        q[d + 2] = t4.z * scale; q[d + 3] = t4.w * scale;
    }

    float o[HD]; float mmax, lsum;
    const float* bk = bqkv_l + C_DIM + h * HD;
    const float* bv = bqkv_l + 2 * C_DIM + h * HD;
    if (tq <= WIN - 1) {
        float s = 0.f;
#pragma unroll
        for (int d = 0; d < HD; d++) s += q[d] * bk[d];
        mmax = s; lsum = 1.f;
#pragma unroll
        for (int d = 0; d < HD; d++) o[d] = bv[d];
    } else {
        mmax = -3.0e38f; lsum = 0.f;
#pragma unroll
        for (int d = 0; d < HD; d++) o[d] = 0.f;
    }

    const int qlo = blockIdx.x * 128;
    const int jstart = (qlo - WIN) > 0 ? (qlo - WIN) : 0;
    const int jend = qlo + 127;

    for (int j0 = jstart; j0 <= jend; j0 += KB) {
        __syncthreads();
#pragma unroll
        for (int i = 0; i < 4; i++) {
            int f = threadIdx.x + i * 128;
            int row = f >> 4;
            int dc = (f & 15) << 2;
            int j = j0 + row;
            float4 kv4 = {0.f,0.f,0.f,0.f}, vv4 = {0.f,0.f,0.f,0.f};
            if (j <= jend) {
                const float* kp = qkv + (size_t)(b * SEQ + j) * (3 * C_DIM) + C_DIM + h * HD + dc;
                kv4 = *(const float4*)kp;
                vv4 = *(const float4*)(kp + C_DIM);
            }
            *(float4*)&Ks[row][dc] = kv4;
            *(float4*)&Vs[row][dc] = vv4;
        }
        __syncthreads();

        for (int jj = 0; jj < KB; jj++) {
            int j = j0 + jj;
            if (j > jend) break;
            if (j > tq || j < tq - WIN) continue;
            float s = 0.f;
#pragma unroll
            for (int d = 0; d < HD; d++) s += q[d] * Ks[jj][d];
            if (s <= mmax) {
                float p = __expf(s - mmax);
                lsum += p;
#pragma unroll
                for (int d = 0; d < HD; d++) o[d] += p * Vs[jj][d];
            } else {
                float cc = __expf(mmax - s);
                lsum = lsum * cc + 1.f;
#pragma unroll
                for (int d = 0; d < HD; d++) o[d] = o[d] * cc + Vs[jj][d];
                mmax = s;
            }
        }
    }

    float rinv = 1.f / lsum;
    size_t off = (size_t)(b * SEQ + tq) * C_DIM + h * HD;
#pragma unroll
    for (int d = 0; d < HD; d += 2) {
        float v0 = o[d] * rinv, v1 = o[d + 1] * rinv;
        __nv_bfloat16 h0, l0, h1, l1;
        split_pair(v0, h0, l0); split_pair(v1, h1, l1);
        __nv_bfloat162 hh; hh.x = h0; hh.y = h1;
        __nv_bfloat162 ll; ll.x = l0; ll.y = l1;
        *(__nv_bfloat162*)(oh + off + d) = hh;
        *(__nv_bfloat162*)(ol + off + d) = ll;
    }
}

// ================= launcher =================
extern "C" void kernel_launch(void* const* d_in, const int* in_sizes, int n_in,
                              void* d_out, int out_size)
{
    const float* x      = (const float*)d_in[0];
    const float* norm_g = (const float*)d_in[1];
    const float* norm_b = (const float*)d_in[2];
    const float* Wqkv   = (const float*)d_in[3];
    const float* bqkv   = (const float*)d_in[4];
    const float* Wo     = (const float*)d_in[5];
    const float* bo     = (const float*)d_in[6];
    const float* ln1_g  = (const float*)d_in[7];
    const float* ln1_b  = (const float*)d_in[8];
    const float* ln2_g  = (const float*)d_in[9];
    const float* ln2_b  = (const float*)d_in[10];
    const float* W1     = (const float*)d_in[11];
    const float* b1     = (const float*)d_in[12];
    const float* W2     = (const float*)d_in[13];
    const float* b2     = (const float*)d_in[14];
    float* out = (float*)d_out;

    float *gx, *gqkv, *gtmp;
    __nv_bfloat16 *gxh, *gxl, *gah, *gal, *ghh, *ghl, *gwh, *gwl;
    cudaGetSymbolAddress((void**)&gx,   g_x);
    cudaGetSymbolAddress((void**)&gqkv, g_qkv);
    cudaGetSymbolAddress((void**)&gtmp, g_tmp);
    cudaGetSymbolAddress((void**)&gxh,  g_xh);  cudaGetSymbolAddress((void**)&gxl, g_xl);
    cudaGetSymbolAddress((void**)&gah,  g_ah);  cudaGetSymbolAddress((void**)&gal, g_al);
    cudaGetSymbolAddress((void**)&ghh,  g_hh);  cudaGetSymbolAddress((void**)&ghl, g_hl);
    cudaGetSymbolAddress((void**)&gwh,  g_wh);  cudaGetSymbolAddress((void**)&gwl, g_wl);

    cudaFuncSetAttribute(gemm_hmma3<0>, cudaFuncAttributeMaxDynamicSharedMemorySize, GEMM_SMEM_BYTES);
    cudaFuncSetAttribute(gemm_hmma3<1>, cudaFuncAttributeMaxDynamicSharedMemorySize, GEMM_SMEM_BYTES);

    const int CONV_BLK = 592;

    embed_ln_kernel<<<NROWS, 256>>>(x, norm_g, norm_b, gx, gxh, gxl);

    for (int l = 0; l < N_LAYERS; l++) {
        const size_t oQ = (size_t)l * 3 * C_DIM * C_DIM;
        const size_t oO = (size_t)l * C_DIM * C_DIM;
        const size_t o1 = (size_t)l * HID_DIM * C_DIM;
        const size_t o2 = (size_t)l * C_DIM * HID_DIM;
        const float* bqkv_l = bqkv + (size_t)l * 3 * C_DIM;

        // qkv = x @ Wqkv^T + bqkv  [4096, 3072], K=1024
        split_f32_kernel<<<CONV_BLK, 256>>>(Wqkv + oQ, gwh, gwl, 3 * C_DIM * C_DIM);
        gemm_hmma3<0><<<dim3(3 * C_DIM / 128, NROWS / 128), 256, GEMM_SMEM_BYTES>>>(
            gxh, gxl, gwh, gwl, bqkv_l, gqkv, nullptr, nullptr,
            NROWS, 3 * C_DIM, C_DIM);

        // attention -> bf16 split
        attn_kernel<<<dim3(SEQ / 128, N_HEADS, BATCH), 128>>>(gqkv, bqkv_l, gah, gal);

        // o = attn @ Wo^T + bo  [4096, 1024], K=1024
        split_f32_kernel<<<CONV_BLK, 256>>>(Wo + oO, gwh, gwl, C_DIM * C_DIM);
        gemm_hmma3<0><<<dim3(C_DIM / 128, NROWS / 128), 256, GEMM_SMEM_BYTES>>>(
            gah, gal, gwh, gwl, bo + (size_t)l * C_DIM, gtmp, nullptr, nullptr,
            NROWS, C_DIM, C_DIM);

        // x = LN(x + o; ln1), emit split
        add_ln_kernel<1><<<NROWS, 256>>>(gx, gtmp, ln1_g + l * C_DIM, ln1_b + l * C_DIM, gx, gxh, gxl);

        // hid = gelu(x @ W1^T + b1) -> bf16 split  [4096, 4096], K=1024
        split_f32_kernel<<<CONV_BLK, 256>>>(W1 + o1, gwh, gwl, HID_DIM * C_DIM);
        gemm_hmma3<1><<<dim3(HID_DIM / 128, NROWS / 128), 256, GEMM_SMEM_BYTES>>>(
            gxh, gxl, gwh, gwl, b1 + (size_t)l * HID_DIM, nullptr, ghh, ghl,
            NROWS, HID_DIM, C_DIM);

        // ff = hid @ W2^T + b2  [4096, 1024], K=4096
        split_f32_kernel<<<CONV_BLK, 256>>>(W2 + o2, gwh, gwl, C_DIM * HID_DIM);
        gemm_hmma3<0><<<dim3(C_DIM / 128, NROWS / 128), 256, GEMM_SMEM_BYTES>>>(
            ghh, ghl, gwh, gwl, b2 + (size_t)l * C_DIM, gtmp, nullptr, nullptr,
            NROWS, C_DIM, HID_DIM);

        // x = LN(x + ff; ln2)
        if (l == N_LAYERS - 1)
            add_ln_kernel<0><<<NROWS, 256>>>(gx, gtmp, ln2_g + l * C_DIM, ln2_b + l * C_DIM, out, nullptr, nullptr);
        else
            add_ln_kernel<1><<<NROWS, 256>>>(gx, gtmp, ln2_g + l * C_DIM, ln2_b + l * C_DIM, gx, gxh, gxl);
    }
}

// round 9
// speedup vs baseline: 3.1468x; 1.4890x over previous
#include <cuda_runtime.h>
#include <cuda_bf16.h>
#include <math.h>
#include <stdint.h>

#define C_DIM   1024
#define N_HEADS 16
#define HD      64
#define N_LAYERS 6
#define HID_DIM 4096
#define BATCH   2
#define SEQ     2048
#define NROWS   (BATCH*SEQ)
#define WIN     1000

// ================= scratch (no allocations allowed) =================
__device__ float g_x   [NROWS * C_DIM];
__device__ float g_tmp [NROWS * C_DIM];
__device__ __nv_bfloat16 g_xh[NROWS * C_DIM],  g_xl[NROWS * C_DIM];
__device__ __nv_bfloat16 g_ah[NROWS * C_DIM],  g_al[NROWS * C_DIM];
__device__ __nv_bfloat16 g_hh[NROWS * HID_DIM], g_hl[NROWS * HID_DIM];
__device__ __nv_bfloat16 g_qkvh[NROWS * 3 * C_DIM], g_qkvl[NROWS * 3 * C_DIM];
// per-layer split weight staging (reused; max 4M elems)
#define WMAX (HID_DIM * C_DIM)
__device__ __nv_bfloat16 g_wh[WMAX], g_wl[WMAX];

// ================= helpers =================
__device__ __forceinline__ uint32_t smem_to_u32(const void* p) {
    uint32_t a;
    asm("{ .reg .u64 t; cvta.to.shared.u64 t, %1; cvt.u32.u64 %0, t; }" : "=r"(a) : "l"(p));
    return a;
}
#define SMEM_SWIZZLE_128B(x) ((x) ^ (((x) >> 3) & 0x70))

__device__ __forceinline__ void ldsm4(uint32_t* r, uint32_t addr) {
    asm volatile("ldmatrix.sync.aligned.m8n8.x4.shared.b16 {%0,%1,%2,%3}, [%4];"
                 : "=r"(r[0]), "=r"(r[1]), "=r"(r[2]), "=r"(r[3]) : "r"(addr));
}
__device__ __forceinline__ void ldsm4t(uint32_t* r, uint32_t addr) {
    asm volatile("ldmatrix.sync.aligned.m8n8.x4.trans.shared.b16 {%0,%1,%2,%3}, [%4];"
                 : "=r"(r[0]), "=r"(r[1]), "=r"(r[2]), "=r"(r[3]) : "r"(addr));
}
__device__ __forceinline__ void mma16816(float* d, const uint32_t* a, uint32_t b0, uint32_t b1) {
    asm volatile("mma.sync.aligned.m16n8k16.row.col.f32.bf16.bf16.f32 "
                 "{%0,%1,%2,%3}, {%4,%5,%6,%7}, {%8,%9}, {%0,%1,%2,%3};"
                 : "+f"(d[0]), "+f"(d[1]), "+f"(d[2]), "+f"(d[3])
                 : "r"(a[0]), "r"(a[1]), "r"(a[2]), "r"(a[3]), "r"(b0), "r"(b1));
}
__device__ __forceinline__ uint32_t packbf(float lo, float hi) {
    uint32_t r;
    asm("cvt.rn.bf16x2.f32 %0, %1, %2;" : "=r"(r) : "f"(hi), "f"(lo));
    return r;
}
__device__ __forceinline__ void split_pair(float v, __nv_bfloat16& hi, __nv_bfloat16& lo) {
    hi = __float2bfloat16(v);
    lo = __float2bfloat16(v - __bfloat162float(hi));
}
#define CPA16(dst, src) \
    asm volatile("cp.async.cg.shared.global [%0], [%1], 16;" :: "r"(dst), "l"(src))

// ================= weight split kernel =================
__global__ void split_f32_kernel(const float* __restrict__ w, __nv_bfloat16* __restrict__ h,
                                 __nv_bfloat16* __restrict__ l, int n) {
    int i = blockIdx.x * blockDim.x + threadIdx.x;
    int stride = gridDim.x * blockDim.x;
    for (; i < n; i += stride) {
        float v = w[i];
        __nv_bfloat16 hi, lo;
        split_pair(v, hi, lo);
        h[i] = hi; l[i] = lo;
    }
}

// ================= block reduce =================
__device__ __forceinline__ float blk_sum(float v, float* sh) {
    int tid = threadIdx.x;
    sh[tid] = v; __syncthreads();
#pragma unroll
    for (int s = 128; s > 0; s >>= 1) { if (tid < s) sh[tid] += sh[tid + s]; __syncthreads(); }
    float r = sh[0]; __syncthreads();
    return r;
}

// ================= input LN + positional embedding =================
__global__ __launch_bounds__(256) void embed_ln_kernel(
    const float* __restrict__ x, const float* __restrict__ g, const float* __restrict__ b,
    float* __restrict__ out, __nv_bfloat16* __restrict__ oh, __nv_bfloat16* __restrict__ ol)
{
    __shared__ float sh[256];
    int r = blockIdx.x, t = r % SEQ, tid = threadIdx.x;
    const float* xr = x + (size_t)r * C_DIM;
    float v[4]; float s = 0.f;
#pragma unroll
    for (int i = 0; i < 4; i++) { v[i] = xr[tid + 256 * i]; s += v[i]; }
    float mean = blk_sum(s, sh) * (1.0f / C_DIM);
    float d2 = 0.f;
#pragma unroll
    for (int i = 0; i < 4; i++) { float d = v[i] - mean; d2 += d * d; }
    float inv = rsqrtf(blk_sum(d2, sh) * (1.0f / C_DIM) + 1e-5f);
    const float kln = 9.2103403719761836f / 511.0f;
    float tf = (float)t;
#pragma unroll
    for (int i = 0; i < 4; i++) {
        int c = tid + 256 * i;
        float ph = (c < 512) ? tf * expf(-((float)c) * kln) : tf * expf(-((float)(c - 512)) * kln);
        float pos = (c < 512) ? cosf(ph) : sinf(ph);
        float y = (v[i] - mean) * inv * g[c] + b[c] + pos;
        size_t idx = (size_t)r * C_DIM + c;
        out[idx] = y;
        __nv_bfloat16 hi, lo; split_pair(y, hi, lo);
        oh[idx] = hi; ol[idx] = lo;
    }
}

// ================= y = LN(xin+add) =================
template<int SPLIT>
__global__ __launch_bounds__(256) void add_ln_kernel(
    const float* __restrict__ xin, const float* __restrict__ add,
    const float* __restrict__ g, const float* __restrict__ b,
    float* __restrict__ out, __nv_bfloat16* __restrict__ oh, __nv_bfloat16* __restrict__ ol)
{
    __shared__ float sh[256];
    int r = blockIdx.x, tid = threadIdx.x;
    const float* xr = xin + (size_t)r * C_DIM;
    const float* ar = add + (size_t)r * C_DIM;
    float v[4]; float s = 0.f;
#pragma unroll
    for (int i = 0; i < 4; i++) { int c = tid + 256 * i; v[i] = xr[c] + ar[c]; s += v[i]; }
    float mean = blk_sum(s, sh) * (1.0f / C_DIM);
    float d2 = 0.f;
#pragma unroll
    for (int i = 0; i < 4; i++) { float d = v[i] - mean; d2 += d * d; }
    float inv = rsqrtf(blk_sum(d2, sh) * (1.0f / C_DIM) + 1e-5f);
#pragma unroll
    for (int i = 0; i < 4; i++) {
        int c = tid + 256 * i;
        float y = (v[i] - mean) * inv * g[c] + b[c];
        size_t idx = (size_t)r * C_DIM + c;
        out[idx] = y;
        if (SPLIT) { __nv_bfloat16 hi, lo; split_pair(y, hi, lo); oh[idx] = hi; ol[idx] = lo; }
    }
}

// ================= split-bf16 HMMA GEMM ===================
// OUT_MODE 0: fp32 + bias. 1: gelu(.)->split. 2: (.)*qscale->split (QKV).
#define GEMM_SMEM_BYTES (1024 + 2 * 4 * 16384)

template<int OUT_MODE>
__global__ __launch_bounds__(256, 1) void gemm_hmma3(
    const __nv_bfloat16* __restrict__ Ah, const __nv_bfloat16* __restrict__ Al,
    const __nv_bfloat16* __restrict__ Bh, const __nv_bfloat16* __restrict__ Bl,
    const float* __restrict__ bias,
    float* __restrict__ Cf, __nv_bfloat16* __restrict__ Ch, __nv_bfloat16* __restrict__ Cl,
    int M, int N, int K)
{
    extern __shared__ char dsm[];
    const uint32_t tiles = (smem_to_u32(dsm) + 1023u) & ~1023u;
    const int tid = threadIdx.x;
    const int wid = tid >> 5;
    const int lid = tid & 31;
    const int warp_m = wid & 1;
    const int warp_n = wid >> 1;
    const int row0 = blockIdx.y * 128;
    const int col0 = blockIdx.x * 128;
    const int nchunk = K >> 6;

    const char* gsrc0 = (const char*)(Ah + (size_t)row0 * K);
    const char* gsrc1 = (const char*)(Al + (size_t)row0 * K);
    const char* gsrc2 = (const char*)(Bh + (size_t)col0 * K);
    const char* gsrc3 = (const char*)(Bl + (size_t)col0 * K);
    const size_t rowbytes = (size_t)K * 2;

    auto load_chunk = [&](int c, int st) {
        const uint32_t sb = tiles + st * 65536;
        const size_t koff = (size_t)c * 128;
#pragma unroll
        for (int i = 0; i < 16; i++) {
            int u = tid + i * 256;
            int t = u >> 10;
            int r = (u >> 3) & 127;
            int cb = (u & 7) * 16;
            const char* g = (t == 0 ? gsrc0 : t == 1 ? gsrc1 : t == 2 ? gsrc2 : gsrc3)
                            + (size_t)r * rowbytes + koff + cb;
            uint32_t sa = sb + t * 16384 + SMEM_SWIZZLE_128B((uint32_t)(r * 128 + cb));
            CPA16(sa, g);
        }
        asm volatile("cp.async.commit_group;");
    };

    float acc[4][4][4];
#pragma unroll
    for (int a = 0; a < 4; a++)
#pragma unroll
        for (int b = 0; b < 4; b++)
#pragma unroll
            for (int i = 0; i < 4; i++) acc[a][b][i] = 0.f;

    const int lane15 = lid & 15;
    const int lanehi = lid >> 4;
    const int xr = lane15 & 7;

    load_chunk(0, 0);

    for (int c = 0; c < nchunk; c++) {
        const int st = c & 1;
        if (c + 1 < nchunk) {
            load_chunk(c + 1, st ^ 1);
            asm volatile("cp.async.wait_group 1;");
        } else {
            asm volatile("cp.async.wait_group 0;");
        }
        __syncthreads();

        const uint32_t sb = tiles + st * 65536;
        const uint32_t aBaseH = sb          + (uint32_t)(warp_m * 64 + lane15) * 128;
        const uint32_t aBaseL = sb + 16384  + (uint32_t)(warp_m * 64 + lane15) * 128;
        const uint32_t bBaseH = sb + 32768  + (uint32_t)(warp_n * 32 + lane15) * 128;
        const uint32_t bBaseL = sb + 49152  + (uint32_t)(warp_n * 32 + lane15) * 128;

#pragma unroll
        for (int ks = 0; ks < 4; ks++) {
            const uint32_t uoff = (uint32_t)(((ks * 2 + lanehi) ^ xr) * 16);
            uint32_t ah[4][4], al[4][4], bhv[2][4], blv[2][4];
#pragma unroll
            for (int mt = 0; mt < 4; mt++) {
                ldsm4(ah[mt], aBaseH + mt * 2048 + uoff);
                ldsm4(al[mt], aBaseL + mt * 2048 + uoff);
            }
#pragma unroll
            for (int pt = 0; pt < 2; pt++) {
                ldsm4(bhv[pt], bBaseH + pt * 2048 + uoff);
                ldsm4(blv[pt], bBaseL + pt * 2048 + uoff);
            }
#pragma unroll
            for (int mt = 0; mt < 4; mt++) {
#pragma unroll
                for (int nt = 0; nt < 4; nt++) {
                    const int pt = nt >> 1, o = nt & 1;
                    mma16816(acc[mt][nt], ah[mt], bhv[pt][o], bhv[pt][o + 2]);
                    mma16816(acc[mt][nt], ah[mt], blv[pt][o], blv[pt][o + 2]);
                    mma16816(acc[mt][nt], al[mt], bhv[pt][o], bhv[pt][o + 2]);
                }
            }
        }
        __syncthreads();
    }

    const int lr = lid >> 2;
    const int lc = (lid & 3) * 2;
#pragma unroll
    for (int mt = 0; mt < 4; mt++) {
        const int row = row0 + warp_m * 64 + mt * 16 + lr;
#pragma unroll
        for (int nt = 0; nt < 4; nt++) {
            const int col = col0 + warp_n * 32 + nt * 8 + lc;
            const float b0 = bias[col], b1 = bias[col + 1];
            float v0 = acc[mt][nt][0] + b0, v1 = acc[mt][nt][1] + b1;
            float v2 = acc[mt][nt][2] + b0, v3 = acc[mt][nt][3] + b1;
            if (OUT_MODE == 0) {
                float2 w0; w0.x = v0; w0.y = v1;
                float2 w1; w1.x = v2; w1.y = v3;
                *(float2*)(Cf + (size_t)row * N + col) = w0;
                *(float2*)(Cf + (size_t)(row + 8) * N + col) = w1;
            } else {
                if (OUT_MODE == 1) {
                    v0 = 0.5f * v0 * (1.f + erff(v0 * 0.70710678118654752f));
                    v1 = 0.5f * v1 * (1.f + erff(v1 * 0.70710678118654752f));
                    v2 = 0.5f * v2 * (1.f + erff(v2 * 0.70710678118654752f));
                    v3 = 0.5f * v3 * (1.f + erff(v3 * 0.70710678118654752f));
                } else {
                    float sc = (col < C_DIM) ? 0.125f : 1.0f;  // scale Q only
                    v0 *= sc; v1 *= sc; v2 *= sc; v3 *= sc;
                }
                __nv_bfloat16 h0, l0, h1, l1, h2, l2, h3, l3;
                split_pair(v0, h0, l0); split_pair(v1, h1, l1);
                split_pair(v2, h2, l2); split_pair(v3, h3, l3);
                __nv_bfloat162 hh0; hh0.x = h0; hh0.y = h1;
                __nv_bfloat162 ll0; ll0.x = l0; ll0.y = l1;
                __nv_bfloat162 hh1; hh1.x = h2; hh1.y = h3;
                __nv_bfloat162 ll1; ll1.x = l2; ll1.y = l3;
                *(__nv_bfloat162*)(Ch + (size_t)row * N + col) = hh0;
                *(__nv_bfloat162*)(Cl + (size_t)row * N + col) = ll0;
                *(__nv_bfloat162*)(Ch + (size_t)(row + 8) * N + col) = hh1;
                *(__nv_bfloat162*)(Cl + (size_t)(row + 8) * N + col) = ll1;
            }
        }
    }
}

// ================= HMMA flash attention (sliding window) ===================
// Block: 128 thr = 4 warps x 16 query rows = 64-query tile for one (b,h).
// S = Qh*Kh + Qh*Kl + Ql*Kh (split-bf16, fp32 acc); online softmax on frags;
// O += P_bf16 * (Vh + Vl). Past zero-token folded via s_past=q.bk, O init=bv.
#define ATTN_SMEM (1024 + 6 * 8192)

__global__ __launch_bounds__(128, 3) void attn_mma_kernel(
    const __nv_bfloat16* __restrict__ qkvh, const __nv_bfloat16* __restrict__ qkvl,
    const float* __restrict__ bqkv_l,
    __nv_bfloat16* __restrict__ oh, __nv_bfloat16* __restrict__ ol)
{
    extern __shared__ char dsm[];
    const uint32_t base = (smem_to_u32(dsm) + 1023u) & ~1023u;
    const uint32_t sQh = base,          sQl = base + 8192;
    const uint32_t sKh = base + 16384,  sKl = base + 24576;
    const uint32_t sVh = base + 32768,  sVl = base + 40960;

    const int tid = threadIdx.x, wid = tid >> 5, lid = tid & 31;
    const int b = blockIdx.z, h = blockIdx.y, q0 = blockIdx.x * 64;
    const int lane15 = lid & 15, lanehi = lid >> 4, xr = lane15 & 7;
    const int tig = lid & 3, gid = lid >> 2;
    const size_t RS = 3 * C_DIM;

    // ---- load Q tile (hi+lo): 64 rows x 128B each ----
#pragma unroll
    for (int i = 0; i < 8; i++) {
        int u = tid + i * 128;          // 0..1023
        int half = u >> 9, idx = u & 511;
        int r = idx >> 3, cu = idx & 7;
        const char* g = (const char*)((half ? qkvl : qkvh)
                        + (size_t)(b * SEQ + q0 + r) * RS + h * HD) + cu * 16;
        uint32_t d = (half ? sQl : sQh) + (uint32_t)(r * 128 + ((cu ^ (r & 7)) * 16));
        CPA16(d, g);
    }
    asm volatile("cp.async.commit_group;");
    asm volatile("cp.async.wait_group 0;");
    __syncthreads();

    // ---- Q A-fragments (held whole kernel) ----
    uint32_t qfh[4][4], qfl[4][4];
    {
        const uint32_t qrb = (uint32_t)((wid * 16 + lane15) * 128);
#pragma unroll
        for (int ks = 0; ks < 4; ks++) {
            const uint32_t uoff = (uint32_t)(((ks * 2 + lanehi) ^ xr) * 16);
            ldsm4(qfh[ks], sQh + qrb + uoff);
            ldsm4(qfl[ks], sQl + qrb + uoff);
        }
    }

    // ---- past zero-token init ----
    const int tq0 = q0 + wid * 16 + gid, tq1 = tq0 + 8;
    const float* bk = bqkv_l + C_DIM + h * HD;
    const float* bv = bqkv_l + 2 * C_DIM + h * HD;
    float sp0 = 0.f, sp1 = 0.f;
    {
        const __nv_bfloat16* q0h = qkvh + (size_t)(b * SEQ + tq0) * RS + h * HD + tig * 16;
        const __nv_bfloat16* q0l = qkvl + (size_t)(b * SEQ + tq0) * RS + h * HD + tig * 16;
        const __nv_bfloat16* q1h = qkvh + (size_t)(b * SEQ + tq1) * RS + h * HD + tig * 16;
        const __nv_bfloat16* q1l = qkvl + (size_t)(b * SEQ + tq1) * RS + h * HD + tig * 16;
#pragma unroll
        for (int dd = 0; dd < 16; dd++) {
            float w = bk[tig * 16 + dd];
            sp0 += (__bfloat162float(q0h[dd]) + __bfloat162float(q0l[dd])) * w;
            sp1 += (__bfloat162float(q1h[dd]) + __bfloat162float(q1l[dd])) * w;
        }
        sp0 += __shfl_xor_sync(0xFFFFFFFF, sp0, 1); sp0 += __shfl_xor_sync(0xFFFFFFFF, sp0, 2);
        sp1 += __shfl_xor_sync(0xFFFFFFFF, sp1, 1); sp1 += __shfl_xor_sync(0xFFFFFFFF, sp1, 2);
    }
    const bool pv0 = (tq0 <= WIN - 1), pv1 = (tq1 <= WIN - 1);
    float m0 = pv0 ? sp0 : -1e30f, m1 = pv1 ? sp1 : -1e30f;
    float l0 = pv0 ? 1.f : 0.f,     l1 = pv1 ? 1.f : 0.f;
    float o[8][4];
#pragma unroll
    for (int nt = 0; nt < 8; nt++) {
        float bva = bv[nt * 8 + 2 * tig], bvb = bv[nt * 8 + 2 * tig + 1];
        o[nt][0] = pv0 ? bva : 0.f; o[nt][1] = pv0 ? bvb : 0.f;
        o[nt][2] = pv1 ? bva : 0.f; o[nt][3] = pv1 ? bvb : 0.f;
    }

    // ---- main loop over 64-key tiles ----
    const int jlo = (q0 > WIN) ? ((q0 - WIN) & ~63) : 0;
    for (int j0 = jlo; j0 < q0 + 64; j0 += 64) {
        __syncthreads();
#pragma unroll
        for (int i = 0; i < 16; i++) {
            int u = tid + i * 128;       // 0..2047
            int t = u >> 9, idx = u & 511;
            int r = idx >> 3, cu = idx & 7;
            const __nv_bfloat16* arr = (t == 0 || t == 2) ? qkvh : qkvl;
            const size_t coloff = ((t < 2) ? C_DIM : 2 * C_DIM) + h * HD;
            const char* g = (const char*)(arr + (size_t)(b * SEQ + j0 + r) * RS + coloff) + cu * 16;
            uint32_t db = (t == 0 ? sKh : t == 1 ? sKl : t == 2 ? sVh : sVl);
            CPA16(db + (uint32_t)(r * 128 + ((cu ^ (r & 7)) * 16)), g);
        }
        asm volatile("cp.async.commit_group;");
        asm volatile("cp.async.wait_group 0;");
        __syncthreads();

        // S = Q.K^T (3-pass split)
        float s[8][4];
#pragma unroll
        for (int nt = 0; nt < 8; nt++)
#pragma unroll
            for (int i = 0; i < 4; i++) s[nt][i] = 0.f;
#pragma unroll
        for (int ks = 0; ks < 4; ks++) {
            const uint32_t uoff = (uint32_t)(((ks * 2 + lanehi) ^ xr) * 16);
            uint32_t kh[4][4], kl[4][4];
#pragma unroll
            for (int pt = 0; pt < 4; pt++) {
                ldsm4(kh[pt], sKh + (uint32_t)((pt * 16 + lane15) * 128) + uoff);
                ldsm4(kl[pt], sKl + (uint32_t)((pt * 16 + lane15) * 128) + uoff);
            }
#pragma unroll
            for (int nt = 0; nt < 8; nt++) {
                const int pt = nt >> 1, oo = nt & 1;
                mma16816(s[nt], qfh[ks], kh[pt][oo], kh[pt][oo + 2]);
                mma16816(s[nt], qfh[ks], kl[pt][oo], kl[pt][oo + 2]);
                mma16816(s[nt], qfl[ks], kh[pt][oo], kh[pt][oo + 2]);
            }
        }
        // mask
#pragma unroll
        for (int nt = 0; nt < 8; nt++)
#pragma unroll
            for (int i = 0; i < 4; i++) {
                int key = j0 + nt * 8 + 2 * tig + (i & 1);
                int tq = (i < 2) ? tq0 : tq1;
                int dlt = tq - key;
                if (dlt < 0 || dlt > WIN) s[nt][i] = -3.0e38f;
            }
        // online softmax
        float mc0 = -3.0e38f, mc1 = -3.0e38f;
#pragma unroll
        for (int nt = 0; nt < 8; nt++) {
            mc0 = fmaxf(mc0, fmaxf(s[nt][0], s[nt][1]));
            mc1 = fmaxf(mc1, fmaxf(s[nt][2], s[nt][3]));
        }
        mc0 = fmaxf(mc0, __shfl_xor_sync(0xFFFFFFFF, mc0, 1));
        mc0 = fmaxf(mc0, __shfl_xor_sync(0xFFFFFFFF, mc0, 2));
        mc1 = fmaxf(mc1, __shfl_xor_sync(0xFFFFFFFF, mc1, 1));
        mc1 = fmaxf(mc1, __shfl_xor_sync(0xFFFFFFFF, mc1, 2));
        float mn0 = fmaxf(m0, mc0), mn1 = fmaxf(m1, mc1);
        float a0 = __expf(m0 - mn0), a1 = __expf(m1 - mn1);
        float rs0 = 0.f, rs1 = 0.f;
#pragma unroll
        for (int nt = 0; nt < 8; nt++) {
            s[nt][0] = __expf(s[nt][0] - mn0); rs0 += s[nt][0];
            s[nt][1] = __expf(s[nt][1] - mn0); rs0 += s[nt][1];
            s[nt][2] = __expf(s[nt][2] - mn1); rs1 += s[nt][2];
            s[nt][3] = __expf(s[nt][3] - mn1); rs1 += s[nt][3];
        }
        rs0 += __shfl_xor_sync(0xFFFFFFFF, rs0, 1); rs0 += __shfl_xor_sync(0xFFFFFFFF, rs0, 2);
        rs1 += __shfl_xor_sync(0xFFFFFFFF, rs1, 1); rs1 += __shfl_xor_sync(0xFFFFFFFF, rs1, 2);
        l0 = l0 * a0 + rs0; l1 = l1 * a1 + rs1;
        m0 = mn0; m1 = mn1;
#pragma unroll
        for (int nt = 0; nt < 8; nt++) {
            o[nt][0] *= a0; o[nt][1] *= a0; o[nt][2] *= a1; o[nt][3] *= a1;
        }
        // pack P -> bf16 A-frags (FA2 register repack)
        uint32_t pa[4][4];
#pragma unroll
        for (int kt = 0; kt < 4; kt++) {
            pa[kt][0] = packbf(s[2 * kt][0],     s[2 * kt][1]);
            pa[kt][1] = packbf(s[2 * kt][2],     s[2 * kt][3]);
            pa[kt][2] = packbf(s[2 * kt + 1][0], s[2 * kt + 1][1]);
            pa[kt][3] = packbf(s[2 * kt + 1][2], s[2 * kt + 1][3]);
        }
        // O += P * (Vh + Vl)
#pragma unroll
        for (int kt = 0; kt < 4; kt++) {
            const uint32_t vrb = (uint32_t)((kt * 16 + lane15) * 128);
            uint32_t vh[4][4], vl[4][4];
#pragma unroll
            for (int j = 0; j < 4; j++) {
                const uint32_t uo = (uint32_t)(((j * 2 + lanehi) ^ xr) * 16);
                ldsm4t(vh[j], sVh + vrb + uo);
                ldsm4t(vl[j], sVl + vrb + uo);
            }
#pragma unroll
            for (int j = 0; j < 4; j++) {
                mma16816(o[2 * j],     pa[kt], vh[j][0], vh[j][1]);
                mma16816(o[2 * j + 1], pa[kt], vh[j][2], vh[j][3]);
                mma16816(o[2 * j],     pa[kt], vl[j][0], vl[j][1]);
                mma16816(o[2 * j + 1], pa[kt], vl[j][2], vl[j][3]);
            }
        }
    }

    // ---- epilogue: normalize + split-bf16 store ----
    const float r0 = 1.f / l0, r1 = 1.f / l1;
#pragma unroll
    for (int nt = 0; nt < 8; nt++) {
        const int col = h * HD + nt * 8 + 2 * tig;
        float v0 = o[nt][0] * r0, v1 = o[nt][1] * r0;
        float v2 = o[nt][2] * r1, v3 = o[nt][3] * r1;
        __nv_bfloat16 h0, lo0, h1, lo1, h2, lo2, h3, lo3;
        split_pair(v0, h0, lo0); split_pair(v1, h1, lo1);
        split_pair(v2, h2, lo2); split_pair(v3, h3, lo3);
        __nv_bfloat162 hh0; hh0.x = h0; hh0.y = h1;
        __nv_bfloat162 ll0; ll0.x = lo0; ll0.y = lo1;
        __nv_bfloat162 hh1; hh1.x = h2; hh1.y = h3;
        __nv_bfloat162 ll1; ll1.x = lo2; ll1.y = lo3;
        *(__nv_bfloat162*)(oh + (size_t)(b * SEQ + tq0) * C_DIM + col) = hh0;
        *(__nv_bfloat162*)(ol + (size_t)(b * SEQ + tq0) * C_DIM + col) = ll0;
        *(__nv_bfloat162*)(oh + (size_t)(b * SEQ + tq1) * C_DIM + col) = hh1;
        *(__nv_bfloat162*)(ol + (size_t)(b * SEQ + tq1) * C_DIM + col) = ll1;
    }
}

// ================= launcher =================
extern "C" void kernel_launch(void* const* d_in, const int* in_sizes, int n_in,
                              void* d_out, int out_size)
{
    const float* x      = (const float*)d_in[0];
    const float* norm_g = (const float*)d_in[1];
    const float* norm_b = (const float*)d_in[2];
    const float* Wqkv   = (const float*)d_in[3];
    const float* bqkv   = (const float*)d_in[4];
    const float* Wo     = (const float*)d_in[5];
    const float* bo     = (const float*)d_in[6];
    const float* ln1_g  = (const float*)d_in[7];
    const float* ln1_b  = (const float*)d_in[8];
    const float* ln2_g  = (const float*)d_in[9];
    const float* ln2_b  = (const float*)d_in[10];
    const float* W1     = (const float*)d_in[11];
    const float* b1     = (const float*)d_in[12];
    const float* W2     = (const float*)d_in[13];
    const float* b2     = (const float*)d_in[14];
    float* out = (float*)d_out;

    float *gx, *gtmp;
    __nv_bfloat16 *gxh, *gxl, *gah, *gal, *ghh, *ghl, *gwh, *gwl, *gqh, *gql;
    cudaGetSymbolAddress((void**)&gx,   g_x);
    cudaGetSymbolAddress((void**)&gtmp, g_tmp);
    cudaGetSymbolAddress((void**)&gxh,  g_xh);  cudaGetSymbolAddress((void**)&gxl, g_xl);
    cudaGetSymbolAddress((void**)&gah,  g_ah);  cudaGetSymbolAddress((void**)&gal, g_al);
    cudaGetSymbolAddress((void**)&ghh,  g_hh);  cudaGetSymbolAddress((void**)&ghl, g_hl);
    cudaGetSymbolAddress((void**)&gwh,  g_wh);  cudaGetSymbolAddress((void**)&gwl, g_wl);
    cudaGetSymbolAddress((void**)&gqh,  g_qkvh); cudaGetSymbolAddress((void**)&gql, g_qkvl);

    cudaFuncSetAttribute(gemm_hmma3<0>, cudaFuncAttributeMaxDynamicSharedMemorySize, GEMM_SMEM_BYTES);
    cudaFuncSetAttribute(gemm_hmma3<1>, cudaFuncAttributeMaxDynamicSharedMemorySize, GEMM_SMEM_BYTES);
    cudaFuncSetAttribute(gemm_hmma3<2>, cudaFuncAttributeMaxDynamicSharedMemorySize, GEMM_SMEM_BYTES);
    cudaFuncSetAttribute(attn_mma_kernel, cudaFuncAttributeMaxDynamicSharedMemorySize, ATTN_SMEM);

    const int CONV_BLK = 592;

    embed_ln_kernel<<<NROWS, 256>>>(x, norm_g, norm_b, gx, gxh, gxl);

    for (int l = 0; l < N_LAYERS; l++) {
        const size_t oQ = (size_t)l * 3 * C_DIM * C_DIM;
        const size_t oO = (size_t)l * C_DIM * C_DIM;
        const size_t o1 = (size_t)l * HID_DIM * C_DIM;
        const size_t o2 = (size_t)l * C_DIM * HID_DIM;
        const float* bqkv_l = bqkv + (size_t)l * 3 * C_DIM;

        // qkv = (x @ Wqkv^T + bqkv), Q scaled by 1/8, split-bf16 out
        split_f32_kernel<<<CONV_BLK, 256>>>(Wqkv + oQ, gwh, gwl, 3 * C_DIM * C_DIM);
        gemm_hmma3<2><<<dim3(3 * C_DIM / 128, NROWS / 128), 256, GEMM_SMEM_BYTES>>>(
            gxh, gxl, gwh, gwl, bqkv_l, nullptr, gqh, gql,
            NROWS, 3 * C_DIM, C_DIM);

        // HMMA flash attention -> split-bf16
        attn_mma_kernel<<<dim3(SEQ / 64, N_HEADS, BATCH), 128, ATTN_SMEM>>>(
            gqh, gql, bqkv_l, gah, gal);

        // o = attn @ Wo^T + bo
        split_f32_kernel<<<CONV_BLK, 256>>>(Wo + oO, gwh, gwl, C_DIM * C_DIM);
        gemm_hmma3<0><<<dim3(C_DIM / 128, NROWS / 128), 256, GEMM_SMEM_BYTES>>>(
            gah, gal, gwh, gwl, bo + (size_t)l * C_DIM, gtmp, nullptr, nullptr,
            NROWS, C_DIM, C_DIM);

        // x = LN(x + o; ln1)
        add_ln_kernel<1><<<NROWS, 256>>>(gx, gtmp, ln1_g + l * C_DIM, ln1_b + l * C_DIM, gx, gxh, gxl);

        // hid = gelu(x @ W1^T + b1) -> split
        split_f32_kernel<<<CONV_BLK, 256>>>(W1 + o1, gwh, gwl, HID_DIM * C_DIM);
        gemm_hmma3<1><<<dim3(HID_DIM / 128, NROWS / 128), 256, GEMM_SMEM_BYTES>>>(
            gxh, gxl, gwh, gwl, b1 + (size_t)l * HID_DIM, nullptr, ghh, ghl,
            NROWS, HID_DIM, C_DIM);

        // ff = hid @ W2^T + b2
        split_f32_kernel<<<CONV_BLK, 256>>>(W2 + o2, gwh, gwl, C_DIM * HID_DIM);
        gemm_hmma3<0><<<dim3(C_DIM / 128, NROWS / 128), 256, GEMM_SMEM_BYTES>>>(
            ghh, ghl, gwh, gwl, b2 + (size_t)l * C_DIM, gtmp, nullptr, nullptr,
            NROWS, C_DIM, HID_DIM);

        // x = LN(x + ff; ln2)
        if (l == N_LAYERS - 1)
            add_ln_kernel<0><<<NROWS, 256>>>(gx, gtmp, ln2_g + l * C_DIM, ln2_b + l * C_DIM, out, nullptr, nullptr);
        else
            add_ln_kernel<1><<<NROWS, 256>>>(gx, gtmp, ln2_g + l * C_DIM, ln2_b + l * C_DIM, gx, gxh, gxl);
    }
}